// round 5
// baseline (speedup 1.0000x reference)
#include <cuda_runtime.h>
#include <cuda_bf16.h>
#include <stdint.h>

// ============================================================================
// Problem constants
// ============================================================================
#define P_PAIRS   524288
#define TILE_M    128
#define NTILES    (P_PAIRS / TILE_M)   // 4096
#define THREADS   512

// ---------------- SMEM layout (single-stage; bytes from base) ---------------
#define OFF_IDX     0         // 256 int32
#define OFF_W3      1024      // 512 floats
#define OFF_OUT     3072      // 256 floats (partial out accum)
// GEMM1 stage (dead after GEMM1):
#define OFF_AHI     4096      // [128 x 64] bf16, 16 KB
#define OFF_ALO     20480
#define OFF_BHI     36864     // [256 x 64] bf16, 32 KB
#define OFF_BLO     69632
// Reused after GEMM1:
#define OFF_X1HI    4096      // 4 tiles x [128 x 64] bf16 = 64 KB
#define OFF_X1LO    69632     // 64 KB
#define OFF_B2HI    135168    // 32 KB
#define OFF_B2LO    167936    // 32 KB
#define SMEM_TOTAL  200704

// ============================================================================
// Device scratch: W1/W2 pre-split to bf16 hi/lo, pre-transposed to [N][K] and
// pre-swizzled as per-64k-chunk [256 x 64] tile images (32 KB each).
// ============================================================================
__device__ __align__(16) unsigned char g_w1hi[262144];
__device__ __align__(16) unsigned char g_w1lo[262144];
__device__ __align__(16) unsigned char g_w2hi[131072];
__device__ __align__(16) unsigned char g_w2lo[131072];
__device__ int g_idx64;   // 1 if dst/src are int64, 0 if int32

// ============================================================================
// Helpers (plain sm_103-level PTX only: ldmatrix / mma.sync / cp.async)
// ============================================================================
__device__ __forceinline__ uint32_t smem_to_u32(const void* p) {
    uint32_t a;
    asm("{ .reg .u64 t; cvta.to.shared.u64 t, %1; cvt.u32.u64 %0, t; }"
        : "=r"(a) : "l"(p));
    return a;
}

#define SWZ128(o) ((o) ^ (((o) >> 3) & 0x70))

#define CP16(dst, src) \
    asm volatile("cp.async.cg.shared.global [%0], [%1], 16;" \
        :: "r"(dst), "l"(src))
#define CP_COMMIT() asm volatile("cp.async.commit_group;")
#define CP_WAIT0()  asm volatile("cp.async.wait_group 0;" ::: "memory")

// ldmatrix.x4: 16x16 bf16 tile from swizzled [rows x 64] (128 B rows) image.
__device__ __forceinline__ void ldsm4(uint32_t* d, uint32_t base, int r0,
                                      int ks, int lane) {
    int r = r0 + (lane & 15);
    uint32_t byte = (uint32_t)(r * 128 + ks * 32 + (lane >> 4) * 16);
    uint32_t addr = base + SWZ128(byte);
    asm volatile("ldmatrix.sync.aligned.m8n8.x4.shared.b16 {%0,%1,%2,%3}, [%4];"
        : "=r"(d[0]), "=r"(d[1]), "=r"(d[2]), "=r"(d[3]) : "r"(addr));
}

__device__ __forceinline__ void mma16816(float* c, const uint32_t* a,
                                         uint32_t b0, uint32_t b1) {
    asm volatile(
        "mma.sync.aligned.m16n8k16.row.col.f32.bf16.bf16.f32 "
        "{%0,%1,%2,%3}, {%4,%5,%6,%7}, {%8,%9}, {%0,%1,%2,%3};"
        : "+f"(c[0]), "+f"(c[1]), "+f"(c[2]), "+f"(c[3])
        : "r"(a[0]), "r"(a[1]), "r"(a[2]), "r"(a[3]), "r"(b0), "r"(b1));
}

__device__ __forceinline__ uint32_t pack_bf2(__nv_bfloat16 a, __nv_bfloat16 b) {
    return (uint32_t)__bfloat16_as_ushort(a) |
           ((uint32_t)__bfloat16_as_ushort(b) << 16);
}

// ============================================================================
// Prologue 1: index dtype detection. Values < 100000, so int64 buffers have
// all odd 32-bit words zero; int32 buffers have random values there.
// ============================================================================
__global__ void detect_idx_kernel(const int* __restrict__ p) {
    if (threadIdx.x == 0) {
        int flag = 1;
        for (int i = 1; i < 256; i += 2)
            if (p[i] != 0) { flag = 0; break; }
        g_idx64 = flag;
    }
}

// ============================================================================
// Prologue 2: split W1/W2 (stored [K][N] row-major) into bf16 hi/lo,
// transposed to [N][K] per-64k-chunk swizzled tile images.
// ============================================================================
__global__ void prep_weights_kernel(const float* __restrict__ W1,
                                    const float* __restrict__ W2) {
    int t = blockIdx.x * blockDim.x + threadIdx.x;
    if (t < 512 * 256) {
        int k = t >> 8, n = t & 255;
        float f = W1[t];
        __nv_bfloat16 hi = __float2bfloat16_rn(f);
        __nv_bfloat16 lo = __float2bfloat16_rn(f - __bfloat162float(hi));
        uint32_t off = (uint32_t)(n * 128 + (k & 63) * 2);
        uint32_t a = SWZ128(off) + (uint32_t)(k >> 6) * 32768u;
        *(unsigned short*)(g_w1hi + a) = __bfloat16_as_ushort(hi);
        *(unsigned short*)(g_w1lo + a) = __bfloat16_as_ushort(lo);
    } else {
        int t2 = t - 512 * 256;
        if (t2 < 256 * 256) {
            int k = t2 >> 8, n = t2 & 255;
            float f = W2[t2];
            __nv_bfloat16 hi = __float2bfloat16_rn(f);
            __nv_bfloat16 lo = __float2bfloat16_rn(f - __bfloat162float(hi));
            uint32_t off = (uint32_t)(n * 128 + (k & 63) * 2);
            uint32_t a = SWZ128(off) + (uint32_t)(k >> 6) * 32768u;
            *(unsigned short*)(g_w2hi + a) = __bfloat16_as_ushort(hi);
            *(unsigned short*)(g_w2lo + a) = __bfloat16_as_ushort(lo);
        }
    }
}

// ============================================================================
// Main fused kernel. CTA = 128 pairs. 16 warps, warp tile 32(M) x 64(N).
// bf16x3 split GEMMs via mma.sync.m16n8k16.
// ============================================================================
__global__ void __launch_bounds__(THREADS, 1)
edge_mlp_kernel(const float* __restrict__ h_nodes,
                const void*  __restrict__ dstp,
                const void*  __restrict__ srcp,
                const float* __restrict__ W3,
                float*       __restrict__ out) {
    extern __shared__ unsigned char smem[];
    uint32_t smem_base = smem_to_u32(smem);
    int tid  = threadIdx.x;
    int lane = tid & 31;
    int wid  = tid >> 5;
    int warp_m = wid & 3;    // 0..3  -> 32 rows each
    int warp_n = wid >> 2;   // 0..3  -> 64 cols each

    // ---- indices, W3, zero out-accum ----
    int gbase = blockIdx.x * TILE_M;
    int* sm_idx = (int*)(smem + OFF_IDX);
    bool i64 = (g_idx64 != 0);
    if (tid < 128) {
        sm_idx[tid] = i64 ? (int)((const long long*)dstp)[gbase + tid]
                          : ((const int*)dstp)[gbase + tid];
    } else if (tid < 256) {
        int t = tid - 128;
        sm_idx[128 + t] = i64 ? (int)((const long long*)srcp)[gbase + t]
                              : ((const int*)srcp)[gbase + t];
    }
    float* w3s = (float*)(smem + OFF_W3);
    w3s[tid] = W3[tid];
    float* sm_out = (float*)(smem + OFF_OUT);
    if (tid < 256) sm_out[tid] = 0.0f;
    __syncthreads();

    float acc[2][8][4];
    #pragma unroll
    for (int a = 0; a < 2; a++)
        #pragma unroll
        for (int b = 0; b < 8; b++)
            #pragma unroll
            for (int c = 0; c < 4; c++) acc[a][b][c] = 0.0f;

    int m_row = tid >> 2;   // 0..127 (gather row)
    int part  = tid & 3;    // 16 floats each

    // ------------------------------------------------------------------
    // GEMM1: D0[128,256] = concat(h[dst],h[src])[128,512] @ W1
    // ------------------------------------------------------------------
    for (int kc = 0; kc < 8; kc++) {
        // B chunk via cp.async (pre-swizzled images)
        {
            const unsigned char* gh = g_w1hi + kc * 32768;
            const unsigned char* gl = g_w1lo + kc * 32768;
            uint32_t dh = smem_base + OFF_BHI;
            uint32_t dl = smem_base + OFF_BLO;
            #pragma unroll
            for (int i = 0; i < 4; i++) {
                uint32_t o = (uint32_t)(tid * 16 + i * 8192);
                CP16(dh + o, gh + o);
                CP16(dl + o, gl + o);
            }
            CP_COMMIT();
        }
        // A chunk: gather + fp32 -> bf16 hi/lo split + swizzled STS
        {
            int idx = sm_idx[((kc < 4) ? 0 : 128) + m_row];
            const float4* rp = (const float4*)(h_nodes + (size_t)idx * 256 +
                                               (kc & 3) * 64) + part * 4;
            unsigned char* ahi = smem + OFF_AHI;
            unsigned char* alo = smem + OFF_ALO;
            #pragma unroll
            for (int q = 0; q < 4; q++) {
                float4 v = rp[q];
                int j0 = part * 16 + q * 4;
                uint32_t sw = SWZ128((uint32_t)(m_row * 128 + j0 * 2));
                __nv_bfloat16 h0 = __float2bfloat16_rn(v.x);
                __nv_bfloat16 h1 = __float2bfloat16_rn(v.y);
                __nv_bfloat16 h2 = __float2bfloat16_rn(v.z);
                __nv_bfloat16 h3 = __float2bfloat16_rn(v.w);
                *(uint32_t*)(ahi + sw)     = pack_bf2(h0, h1);
                *(uint32_t*)(ahi + sw + 4) = pack_bf2(h2, h3);
                __nv_bfloat16 l0 = __float2bfloat16_rn(v.x - __bfloat162float(h0));
                __nv_bfloat16 l1 = __float2bfloat16_rn(v.y - __bfloat162float(h1));
                __nv_bfloat16 l2 = __float2bfloat16_rn(v.z - __bfloat162float(h2));
                __nv_bfloat16 l3 = __float2bfloat16_rn(v.w - __bfloat162float(h3));
                *(uint32_t*)(alo + sw)     = pack_bf2(l0, l1);
                *(uint32_t*)(alo + sw + 4) = pack_bf2(l2, l3);
            }
        }
        CP_WAIT0();
        __syncthreads();
        // compute 64-k chunk
        uint32_t aHiB = smem_base + OFF_AHI, aLoB = smem_base + OFF_ALO;
        uint32_t bHiB = smem_base + OFF_BHI, bLoB = smem_base + OFF_BLO;
        #pragma unroll
        for (int ks = 0; ks < 4; ks++) {
            uint32_t ah[2][4], al[2][4];
            #pragma unroll
            for (int mf = 0; mf < 2; mf++) {
                ldsm4(ah[mf], aHiB, warp_m * 32 + mf * 16, ks, lane);
                ldsm4(al[mf], aLoB, warp_m * 32 + mf * 16, ks, lane);
            }
            #pragma unroll
            for (int ng = 0; ng < 4; ng++) {
                uint32_t bh[4], bl[4];
                ldsm4(bh, bHiB, warp_n * 64 + ng * 16, ks, lane);
                ldsm4(bl, bLoB, warp_n * 64 + ng * 16, ks, lane);
                #pragma unroll
                for (int mf = 0; mf < 2; mf++) {
                    mma16816(acc[mf][ng * 2 + 0], ah[mf], bh[0], bh[2]);
                    mma16816(acc[mf][ng * 2 + 1], ah[mf], bh[1], bh[3]);
                    mma16816(acc[mf][ng * 2 + 0], ah[mf], bl[0], bl[2]);
                    mma16816(acc[mf][ng * 2 + 1], ah[mf], bl[1], bl[3]);
                    mma16816(acc[mf][ng * 2 + 0], al[mf], bh[0], bh[2]);
                    mma16816(acc[mf][ng * 2 + 1], al[mf], bh[1], bh[3]);
                }
            }
        }
        __syncthreads();
    }

    // ------------------------------------------------------------------
    // Epilogue 1: ReLU + bf16 hi/lo split -> X1 (4 chunk tiles, swizzled)
    // ------------------------------------------------------------------
    {
        unsigned char* x1h = smem + OFF_X1HI + warp_n * 16384;
        unsigned char* x1l = smem + OFF_X1LO + warp_n * 16384;
        int r0 = warp_m * 32 + (lane >> 2);
        int qb = 2 * (lane & 3);
        #pragma unroll
        for (int mf = 0; mf < 2; mf++) {
            #pragma unroll
            for (int nf = 0; nf < 8; nf++) {
                int qq = nf * 8 + qb;
                #pragma unroll
                for (int half = 0; half < 2; half++) {
                    float v0 = acc[mf][nf][half * 2 + 0];
                    float v1 = acc[mf][nf][half * 2 + 1];
                    v0 = v0 > 0.f ? v0 : 0.f;
                    v1 = v1 > 0.f ? v1 : 0.f;
                    __nv_bfloat16 h0 = __float2bfloat16_rn(v0);
                    __nv_bfloat16 h1 = __float2bfloat16_rn(v1);
                    __nv_bfloat16 l0 = __float2bfloat16_rn(v0 - __bfloat162float(h0));
                    __nv_bfloat16 l1 = __float2bfloat16_rn(v1 - __bfloat162float(h1));
                    int row = r0 + mf * 16 + half * 8;
                    uint32_t sw = SWZ128((uint32_t)(row * 128 + qq * 2));
                    *(uint32_t*)(x1h + sw) = pack_bf2(h0, h1);
                    *(uint32_t*)(x1l + sw) = pack_bf2(l0, l1);
                }
            }
        }
    }

    // re-zero accumulators for GEMM2
    #pragma unroll
    for (int a = 0; a < 2; a++)
        #pragma unroll
        for (int b = 0; b < 8; b++)
            #pragma unroll
            for (int c = 0; c < 4; c++) acc[a][b][c] = 0.0f;

    // ------------------------------------------------------------------
    // GEMM2: D1[128,256] = X1[128,256] @ W2
    // ------------------------------------------------------------------
    for (int kc = 0; kc < 4; kc++) {
        {
            const unsigned char* gh = g_w2hi + kc * 32768;
            const unsigned char* gl = g_w2lo + kc * 32768;
            uint32_t dh = smem_base + OFF_B2HI;
            uint32_t dl = smem_base + OFF_B2LO;
            #pragma unroll
            for (int i = 0; i < 4; i++) {
                uint32_t o = (uint32_t)(tid * 16 + i * 8192);
                CP16(dh + o, gh + o);
                CP16(dl + o, gl + o);
            }
            CP_COMMIT();
        }
        CP_WAIT0();
        __syncthreads();   // also publishes epilogue-1 X1 writes on kc==0
        uint32_t aHiB = smem_base + OFF_X1HI + kc * 16384;
        uint32_t aLoB = smem_base + OFF_X1LO + kc * 16384;
        uint32_t bHiB = smem_base + OFF_B2HI, bLoB = smem_base + OFF_B2LO;
        #pragma unroll
        for (int ks = 0; ks < 4; ks++) {
            uint32_t ah[2][4], al[2][4];
            #pragma unroll
            for (int mf = 0; mf < 2; mf++) {
                ldsm4(ah[mf], aHiB, warp_m * 32 + mf * 16, ks, lane);
                ldsm4(al[mf], aLoB, warp_m * 32 + mf * 16, ks, lane);
            }
            #pragma unroll
            for (int ng = 0; ng < 4; ng++) {
                uint32_t bh[4], bl[4];
                ldsm4(bh, bHiB, warp_n * 64 + ng * 16, ks, lane);
                ldsm4(bl, bLoB, warp_n * 64 + ng * 16, ks, lane);
                #pragma unroll
                for (int mf = 0; mf < 2; mf++) {
                    mma16816(acc[mf][ng * 2 + 0], ah[mf], bh[0], bh[2]);
                    mma16816(acc[mf][ng * 2 + 1], ah[mf], bh[1], bh[3]);
                    mma16816(acc[mf][ng * 2 + 0], ah[mf], bl[0], bl[2]);
                    mma16816(acc[mf][ng * 2 + 1], ah[mf], bl[1], bl[3]);
                    mma16816(acc[mf][ng * 2 + 0], al[mf], bh[0], bh[2]);
                    mma16816(acc[mf][ng * 2 + 1], al[mf], bh[1], bh[3]);
                }
            }
        }
        __syncthreads();
    }

    // ------------------------------------------------------------------
    // Epilogue 2 (fused GEMM3): out[m,:] = ReLU(D1[m,:]) @ W3[256,2]
    // ------------------------------------------------------------------
    {
        float p[4][2];
        #pragma unroll
        for (int r = 0; r < 4; r++) { p[r][0] = 0.f; p[r][1] = 0.f; }
        int qb = 2 * (lane & 3);
        #pragma unroll
        for (int mf = 0; mf < 2; mf++) {
            #pragma unroll
            for (int nf = 0; nf < 8; nf++) {
                #pragma unroll
                for (int i = 0; i < 4; i++) {
                    float v = acc[mf][nf][i];
                    v = v > 0.f ? v : 0.f;
                    int rsel = mf * 2 + (i >> 1);
                    int n = warp_n * 64 + nf * 8 + qb + (i & 1);
                    p[rsel][0] = fmaf(v, w3s[2 * n],     p[rsel][0]);
                    p[rsel][1] = fmaf(v, w3s[2 * n + 1], p[rsel][1]);
                }
            }
        }
        // reduce over the 4 lanes sharing each row (lane bits 0-1)
        #pragma unroll
        for (int r = 0; r < 4; r++) {
            #pragma unroll
            for (int c = 0; c < 2; c++) {
                p[r][c] += __shfl_xor_sync(0xffffffffu, p[r][c], 1);
                p[r][c] += __shfl_xor_sync(0xffffffffu, p[r][c], 2);
            }
        }
        if ((lane & 3) == 0) {
            #pragma unroll
            for (int r = 0; r < 4; r++) {
                int row = warp_m * 32 + (r >> 1) * 16 + (r & 1) * 8 + (lane >> 2);
                atomicAdd(&sm_out[row * 2 + 0], p[r][0]);
                atomicAdd(&sm_out[row * 2 + 1], p[r][1]);
            }
        }
    }
    __syncthreads();
    if (tid < 256)
        out[(size_t)gbase * 2 + tid] = sm_out[tid];
}

// ============================================================================
// Launch
// ============================================================================
extern "C" void kernel_launch(void* const* d_in, const int* in_sizes, int n_in,
                              void* d_out, int out_size) {
    const float* h_nodes = (const float*)d_in[0];
    const void*  dstp    = d_in[1];
    const void*  srcp    = d_in[2];
    const float* W1      = (const float*)d_in[3];
    const float* W2      = (const float*)d_in[4];
    const float* W3      = (const float*)d_in[5];
    float*       out     = (float*)d_out;

    detect_idx_kernel<<<1, 32>>>((const int*)dstp);
    prep_weights_kernel<<<768, 256>>>(W1, W2);

    cudaFuncSetAttribute(edge_mlp_kernel,
                         cudaFuncAttributeMaxDynamicSharedMemorySize, SMEM_TOTAL);
    edge_mlp_kernel<<<NTILES, THREADS, SMEM_TOTAL>>>(h_nodes, dstp, srcp, W3, out);
}